// round 1
// baseline (speedup 1.0000x reference)
#include <cuda_runtime.h>
#include <math.h>

// Problem constants
#define B_    8
#define NE    4
#define Tn    1024
#define D_    1024
#define G_    8
#define BLK   128
#define TT    64
#define DLLM  2048
#define NT    (B_*NE*Tn)          // 32768 tokens
#define SCALEF 0.08838834764831845f  // 128^-0.5

// -------- device scratch (no dynamic allocation allowed) --------
__device__ float g_kvp[16*2*8*64*128];   // K-split partials for k/v
__device__ float g_k[B_*TT*BLK];         // [8][64][128]
__device__ float g_v[B_*TT*BLK];
__device__ float g_A[NT*BLK];            // gate*gamma
__device__ float g_B[NT*BLK];            // gate*beta

// ============================================================================
// Kernel 1: k/v projection, split-K GEMM.
// grid = 256 blocks: slice(16) x b(8) x which(2). Each block: 64 s x 128 o,
// K-range of 128 (two 64-wide inner chunks). Partials to g_kvp.
// smem: ws[64][132] transposed weight chunk + xs[64][64] h_llm chunk.
// ============================================================================
__global__ void kv_kernel(const float* __restrict__ h_llm,
                          const float* __restrict__ Wk,
                          const float* __restrict__ Wv) {
    extern __shared__ float sm[];
    float* ws = sm;              // [64][132]  = 8448 floats
    float* xs = sm + 64*132;     // [64][64]   = 4096 floats
    int bx = blockIdx.x;
    int slice = bx >> 4;
    int b     = (bx >> 1) & 7;
    int which = bx & 1;
    const float* W = which ? Wv : Wk;
    int kbase = slice * 128;
    int tid = threadIdx.x;
    int oq = tid & 31, sg = tid >> 5;
    int o0 = oq * 4;

    float acc[8][4];
    #pragma unroll
    for (int r = 0; r < 8; r++)
        #pragma unroll
        for (int j = 0; j < 4; j++) acc[r][j] = 0.f;

    for (int kc = 0; kc < 128; kc += 64) {
        __syncthreads();
        for (int idx = tid; idx < 64*64; idx += 256) {
            int s = idx >> 6, i = idx & 63;
            xs[s*64 + i] = h_llm[(size_t)b*TT*DLLM + (size_t)s*DLLM + kbase + kc + i];
        }
        for (int idx = tid; idx < 128*64; idx += 256) {
            int o = idx >> 6, i = idx & 63;
            ws[i*132 + o] = W[(size_t)o*DLLM + kbase + kc + i];
        }
        __syncthreads();
        for (int i = 0; i < 64; i++) {
            float4 w4 = *(const float4*)&ws[i*132 + o0];
            #pragma unroll
            for (int r = 0; r < 8; r++) {
                float x = xs[(sg*8 + r)*64 + i];
                acc[r][0] += x * w4.x; acc[r][1] += x * w4.y;
                acc[r][2] += x * w4.z; acc[r][3] += x * w4.w;
            }
        }
    }
    float* outp = g_kvp + ((size_t)(slice*2 + which)*8 + b) * (64*128);
    #pragma unroll
    for (int r = 0; r < 8; r++) {
        int s = sg*8 + r;
        float4 v4 = make_float4(acc[r][0], acc[r][1], acc[r][2], acc[r][3]);
        *(float4*)&outp[s*128 + o0] = v4;
    }
}

// Reduce the 16 K-slices + bias -> g_k / g_v. Deterministic (fixed order).
__global__ void kv_reduce(const float* __restrict__ bk,
                          const float* __restrict__ bv) {
    int idx = blockIdx.x * 256 + threadIdx.x;
    if (idx >= 2*8*64*128) return;
    int which = idx >> 16;        // 0=k, 1=v
    int rem   = idx & 65535;      // b*8192 + s*128 + o
    int o = rem & 127;
    float s = which ? bv[o] : bk[o];
    #pragma unroll
    for (int sl = 0; sl < 16; sl++)
        s += g_kvp[(size_t)(sl*2 + which)*65536 + rem];
    (which ? g_v : g_k)[rem] = s;
}

// ============================================================================
// Kernel 2: "mega" — per 64-token tile (one batch):
//   maxpool(inv) -> q = inv@WqT+bq (pre-scaled) -> scores vs k -> softmax
//   -> ctx = attn@v -> A = sigmoid(ctx)*(ctx@WgT+bg), B = sigmoid(ctx)*(ctx@WbT+bb)
// smem arenas (floats): ws 16896 | xs 8192 | ss 4160 | qs 8704  = 151808 B
// ============================================================================
#define MEGA_SMEM ((16896 + 8192 + 4160 + 8704) * 4)

__global__ void mega_kernel(const float* __restrict__ h_prime,
                            const float* __restrict__ Wq, const float* __restrict__ bq,
                            const float* __restrict__ Wg, const float* __restrict__ bg,
                            const float* __restrict__ Wb, const float* __restrict__ bb) {
    extern __shared__ float sm[];
    float* ws = sm;                 // WqT[128][132] / (ks_t[128][68]+vs[64][128]) / WgT / WbT
    float* xs = sm + 16896;         // inv tile [64][128], later ctx tile
    float* ss = xs + 8192;          // scores [64][65]
    float* qs = ss + 4160;          // q transposed [128][68]

    int tid = threadIdx.x;
    int t0  = blockIdx.x * 64;
    int b   = t0 >> 12;             // 4096 tokens per batch
    int oq  = tid & 31, tg = tid >> 5;
    int o0  = oq * 4;

    // ---- P0: inv = max over groups; WqT into ws ----
    for (int idx = tid; idx < 8192; idx += 256) {
        int t = idx >> 7, j = idx & 127;
        const float* hp = h_prime + (size_t)(t0 + t)*1024 + j;
        float m = hp[0];
        #pragma unroll
        for (int g = 1; g < 8; g++) m = fmaxf(m, hp[g*128]);
        xs[idx] = m;
    }
    for (int idx = tid; idx < 16384; idx += 256) {
        int o = idx >> 7, i = idx & 127;
        ws[i*132 + o] = Wq[idx];
    }
    __syncthreads();

    // ---- P1: q = inv @ WqT + bq, pre-multiplied by SCALE, into qs[d][t] ----
    {
        float acc[8][4];
        #pragma unroll
        for (int r = 0; r < 8; r++)
            #pragma unroll
            for (int j = 0; j < 4; j++) acc[r][j] = 0.f;
        for (int i = 0; i < 128; i++) {
            float4 w4 = *(const float4*)&ws[i*132 + o0];
            #pragma unroll
            for (int r = 0; r < 8; r++) {
                float x = xs[(tg*8 + r)*128 + i];
                acc[r][0] += x * w4.x; acc[r][1] += x * w4.y;
                acc[r][2] += x * w4.z; acc[r][3] += x * w4.w;
            }
        }
        float4 bq4 = *(const float4*)&bq[o0];
        #pragma unroll
        for (int r = 0; r < 8; r++) {
            int t = tg*8 + r;
            qs[(o0+0)*68 + t] = (acc[r][0] + bq4.x) * SCALEF;
            qs[(o0+1)*68 + t] = (acc[r][1] + bq4.y) * SCALEF;
            qs[(o0+2)*68 + t] = (acc[r][2] + bq4.z) * SCALEF;
            qs[(o0+3)*68 + t] = (acc[r][3] + bq4.w) * SCALEF;
        }
    }
    __syncthreads();

    // ---- P2: load k (transposed) + v for this batch into ws ----
    for (int idx = tid; idx < 8192; idx += 256) {
        int s = idx >> 7, d = idx & 127;
        float kvval = g_k[(size_t)b*8192 + idx];
        ws[d*68 + s]  = kvval;                       // ks_t[128][68]
        ws[8704 + idx] = g_v[(size_t)b*8192 + idx];  // vs[64][128]
    }
    __syncthreads();

    // ---- scores[t][s] = q(t)·k(s) (scale folded into q) ----
    {
        int t4 = tid & 15, s4 = tid >> 4;
        int tt0 = t4*4, s0 = s4*4;
        float acc[4][4];
        #pragma unroll
        for (int a = 0; a < 4; a++)
            #pragma unroll
            for (int c = 0; c < 4; c++) acc[a][c] = 0.f;
        for (int d = 0; d < 128; d++) {
            float4 q4 = *(const float4*)&qs[d*68 + tt0];
            float4 k4 = *(const float4*)&ws[d*68 + s0];
            acc[0][0]+=q4.x*k4.x; acc[0][1]+=q4.x*k4.y; acc[0][2]+=q4.x*k4.z; acc[0][3]+=q4.x*k4.w;
            acc[1][0]+=q4.y*k4.x; acc[1][1]+=q4.y*k4.y; acc[1][2]+=q4.y*k4.z; acc[1][3]+=q4.y*k4.w;
            acc[2][0]+=q4.z*k4.x; acc[2][1]+=q4.z*k4.y; acc[2][2]+=q4.z*k4.z; acc[2][3]+=q4.z*k4.w;
            acc[3][0]+=q4.w*k4.x; acc[3][1]+=q4.w*k4.y; acc[3][2]+=q4.w*k4.z; acc[3][3]+=q4.w*k4.w;
        }
        #pragma unroll
        for (int a = 0; a < 4; a++)
            #pragma unroll
            for (int c = 0; c < 4; c++)
                ss[(tt0 + a)*65 + s0 + c] = acc[a][c];
    }
    __syncthreads();

    // ---- softmax over s (64) per token row ----
    if (tid < 64) {
        float* row = ss + tid*65;
        float m = row[0];
        for (int s = 1; s < 64; s++) m = fmaxf(m, row[s]);
        float sum = 0.f;
        for (int s = 0; s < 64; s++) { float e = __expf(row[s] - m); row[s] = e; sum += e; }
        float inv = 1.f / sum;
        for (int s = 0; s < 64; s++) row[s] *= inv;
    }
    __syncthreads();

    // ---- ctx = attn @ v  -> overwrite xs ----
    {
        const float* vs = ws + 8704;
        float acc[8][4];
        #pragma unroll
        for (int r = 0; r < 8; r++)
            #pragma unroll
            for (int j = 0; j < 4; j++) acc[r][j] = 0.f;
        for (int s = 0; s < 64; s++) {
            float4 v4 = *(const float4*)&vs[s*128 + o0];
            #pragma unroll
            for (int r = 0; r < 8; r++) {
                float p = ss[(tg*8 + r)*65 + s];
                acc[r][0] += p * v4.x; acc[r][1] += p * v4.y;
                acc[r][2] += p * v4.z; acc[r][3] += p * v4.w;
            }
        }
        #pragma unroll
        for (int r = 0; r < 8; r++) {
            int t = tg*8 + r;
            xs[t*128 + o0 + 0] = acc[r][0];
            xs[t*128 + o0 + 1] = acc[r][1];
            xs[t*128 + o0 + 2] = acc[r][2];
            xs[t*128 + o0 + 3] = acc[r][3];
        }
    }
    __syncthreads();

    // ---- P5: A = sigmoid(ctx) * (ctx @ WgT + bg) ----
    for (int idx = tid; idx < 16384; idx += 256) {
        int o = idx >> 7, i = idx & 127;
        ws[i*132 + o] = Wg[idx];
    }
    __syncthreads();
    {
        float acc[8][4];
        #pragma unroll
        for (int r = 0; r < 8; r++)
            #pragma unroll
            for (int j = 0; j < 4; j++) acc[r][j] = 0.f;
        for (int i = 0; i < 128; i++) {
            float4 w4 = *(const float4*)&ws[i*132 + o0];
            #pragma unroll
            for (int r = 0; r < 8; r++) {
                float x = xs[(tg*8 + r)*128 + i];
                acc[r][0] += x * w4.x; acc[r][1] += x * w4.y;
                acc[r][2] += x * w4.z; acc[r][3] += x * w4.w;
            }
        }
        float4 bg4 = *(const float4*)&bg[o0];
        #pragma unroll
        for (int r = 0; r < 8; r++) {
            int t = tg*8 + r;
            float4 c4 = *(const float4*)&xs[t*128 + o0];
            float4 res;
            res.x = (1.f/(1.f+__expf(-c4.x))) * (acc[r][0] + bg4.x);
            res.y = (1.f/(1.f+__expf(-c4.y))) * (acc[r][1] + bg4.y);
            res.z = (1.f/(1.f+__expf(-c4.z))) * (acc[r][2] + bg4.z);
            res.w = (1.f/(1.f+__expf(-c4.w))) * (acc[r][3] + bg4.w);
            *(float4*)&g_A[(size_t)(t0 + t)*128 + o0] = res;
        }
    }
    __syncthreads();

    // ---- P6: B = sigmoid(ctx) * (ctx @ WbT + bb) ----
    for (int idx = tid; idx < 16384; idx += 256) {
        int o = idx >> 7, i = idx & 127;
        ws[i*132 + o] = Wb[idx];
    }
    __syncthreads();
    {
        float acc[8][4];
        #pragma unroll
        for (int r = 0; r < 8; r++)
            #pragma unroll
            for (int j = 0; j < 4; j++) acc[r][j] = 0.f;
        for (int i = 0; i < 128; i++) {
            float4 w4 = *(const float4*)&ws[i*132 + o0];
            #pragma unroll
            for (int r = 0; r < 8; r++) {
                float x = xs[(tg*8 + r)*128 + i];
                acc[r][0] += x * w4.x; acc[r][1] += x * w4.y;
                acc[r][2] += x * w4.z; acc[r][3] += x * w4.w;
            }
        }
        float4 bb4 = *(const float4*)&bb[o0];
        #pragma unroll
        for (int r = 0; r < 8; r++) {
            int t = tg*8 + r;
            float4 c4 = *(const float4*)&xs[t*128 + o0];
            float4 res;
            res.x = (1.f/(1.f+__expf(-c4.x))) * (acc[r][0] + bb4.x);
            res.y = (1.f/(1.f+__expf(-c4.y))) * (acc[r][1] + bb4.y);
            res.z = (1.f/(1.f+__expf(-c4.z))) * (acc[r][2] + bb4.z);
            res.w = (1.f/(1.f+__expf(-c4.w))) * (acc[r][3] + bb4.w);
            *(float4*)&g_B[(size_t)(t0 + t)*128 + o0] = res;
        }
    }
}

// ============================================================================
// Kernel 3: final — equi GEMM (We per group slice) fused with FiLM + residual.
// grid = 4096 blocks, 8 tokens/block, warp-per-token, 32 accumulators/thread.
// smem: WeT[128][132] + h tile [8][1024] + A/B tiles -> 108544 B.
// ============================================================================
#define FINAL_SMEM ((16896 + 8192 + 1024 + 1024) * 4)

__global__ void final_kernel(const float* __restrict__ h_prime,
                             const float* __restrict__ We,
                             float* __restrict__ out) {
    extern __shared__ float sm[];
    float* ws = sm;               // WeT [128][132]
    float* hs = sm + 16896;       // [8][1024]
    float* As = hs + 8192;        // [8][128]
    float* Bs = As + 1024;        // [8][128]

    int tid = threadIdx.x;
    size_t t0 = (size_t)blockIdx.x * 8;

    for (int idx = tid; idx < 16384; idx += 256) {
        int o = idx >> 7, i = idx & 127;
        ws[i*132 + o] = We[idx];
    }
    for (int idx = tid; idx < 8192; idx += 256)
        hs[idx] = h_prime[t0*1024 + idx];
    for (int idx = tid; idx < 1024; idx += 256) {
        As[idx] = g_A[t0*128 + idx];
        Bs[idx] = g_B[t0*128 + idx];
    }
    __syncthreads();

    int oq = tid & 31, t = tid >> 5;     // warp-per-token
    int o0 = oq * 4;
    const float* hrow = hs + t*1024;

    float acc[8][4];
    #pragma unroll
    for (int g = 0; g < 8; g++)
        #pragma unroll
        for (int j = 0; j < 4; j++) acc[g][j] = 0.f;

    for (int i = 0; i < 128; i++) {
        float4 w4 = *(const float4*)&ws[i*132 + o0];
        #pragma unroll
        for (int g = 0; g < 8; g++) {
            float x = hrow[g*128 + i];
            acc[g][0] += x * w4.x; acc[g][1] += x * w4.y;
            acc[g][2] += x * w4.z; acc[g][3] += x * w4.w;
        }
    }

    float4 A4 = *(const float4*)&As[t*128 + o0];
    float4 B4 = *(const float4*)&Bs[t*128 + o0];
    #pragma unroll
    for (int g = 0; g < 8; g++) {
        float4 res;
        res.x = hrow[g*128 + o0 + 0] + A4.x * acc[g][0] + B4.x;
        res.y = hrow[g*128 + o0 + 1] + A4.y * acc[g][1] + B4.y;
        res.z = hrow[g*128 + o0 + 2] + A4.z * acc[g][2] + B4.z;
        res.w = hrow[g*128 + o0 + 3] + A4.w * acc[g][3] + B4.w;
        *(float4*)&out[(t0 + t)*1024 + g*128 + o0] = res;
    }
}

// ============================================================================
extern "C" void kernel_launch(void* const* d_in, const int* in_sizes, int n_in,
                              void* d_out, int out_size) {
    const float* h_prime = (const float*)d_in[0];
    const float* h_llm   = (const float*)d_in[1];
    const float* Wq = (const float*)d_in[2];
    const float* bq = (const float*)d_in[3];
    const float* Wk = (const float*)d_in[4];
    const float* bk = (const float*)d_in[5];
    const float* Wv = (const float*)d_in[6];
    const float* bv = (const float*)d_in[7];
    const float* Wg = (const float*)d_in[8];
    const float* bg = (const float*)d_in[9];
    const float* Wb = (const float*)d_in[10];
    const float* bb = (const float*)d_in[11];
    const float* We = (const float*)d_in[12];
    float* out = (float*)d_out;

    const int KV_SMEM = (8448 + 4096) * 4;   // 50176
    cudaFuncSetAttribute(kv_kernel,    cudaFuncAttributeMaxDynamicSharedMemorySize, KV_SMEM);
    cudaFuncSetAttribute(mega_kernel,  cudaFuncAttributeMaxDynamicSharedMemorySize, MEGA_SMEM);
    cudaFuncSetAttribute(final_kernel, cudaFuncAttributeMaxDynamicSharedMemorySize, FINAL_SMEM);

    kv_kernel<<<256, 256, KV_SMEM>>>(h_llm, Wk, Wv);
    kv_reduce<<<512, 256>>>(bk, bv);
    mega_kernel<<<512, 256, MEGA_SMEM>>>(h_prime, Wq, bq, Wg, bg, Wb, bb);
    final_kernel<<<4096, 256, FINAL_SMEM>>>(h_prime, We, out);
}